// round 2
// baseline (speedup 1.0000x reference)
#include <cuda_runtime.h>
#include <cuda_bf16.h>
#include <math.h>

// Problem constants
#define NN 50000
#define NE 800000
#define DD 128
#define NC 2

// ---------------- scratch (static device memory; no allocation) ----------------
__device__ float g_deg[NN];       // degree (with self loop)
__device__ float g_inv[NN];       // deg^{-1/2}
__device__ float g_h[NN * DD];    // GEMM output (h = in @ W)
__device__ float g_agg[NN * DD];  // aggregation buffer / post-ReLU activations
__device__ float g_pool[DD];      // column sums for mean pool

// ---------------- init: deg = 1 (self loop), pool = 0 ----------------
__global__ void k_init(float* deg, float* pool) {
    int i = blockIdx.x * blockDim.x + threadIdx.x;
    if (i < NN) deg[i] = 1.0f;
    if (i < DD) pool[i] = 0.0f;
}

// ---------------- count in-degrees over dst ----------------
__global__ void k_count(const int* __restrict__ dst, float* __restrict__ deg) {
    int e = blockIdx.x * blockDim.x + threadIdx.x;
    if (e < NE) atomicAdd(&deg[dst[e]], 1.0f);
}

// ---------------- inv_sqrt ----------------
__global__ void k_rsqrt(const float* __restrict__ deg, float* __restrict__ inv) {
    int i = blockIdx.x * blockDim.x + threadIdx.x;
    if (i < NN) inv[i] = rsqrtf(deg[i]);
}

// ---------------- GEMM: h[n,128] = A[n,128] @ W[128,128]; agg = h * (1/deg) ----
// Block: 64 rows x 128 cols, 256 threads. Full W in smem (64KB).
// Thread tile: 8 rows x 4 cols = 32 accumulators. 3x LDS.128 per 32 FMA.
// Epilogue writes both h and the self-loop-initialized aggregation buffer.
#define XS_PITCH 68
__global__ void __launch_bounds__(256, 2)
k_gemm(const float* __restrict__ A, const float* __restrict__ W,
       const float* __restrict__ inv,
       float* __restrict__ H, float* __restrict__ AGG, int n) {
    extern __shared__ float sm[];
    float* ws = sm;                 // 128*128
    float* xs = sm + DD * DD;       // 16 * XS_PITCH

    const int tid = threadIdx.x;
    const int tx  = tid & 31;       // col group -> cols tx*4 .. tx*4+3
    const int ty  = tid >> 5;       // row group -> rows ty*8 .. ty*8+7
    const int row0 = blockIdx.x * 64;

    // load full W (row-major [k][c]) into smem, coalesced float4
    #pragma unroll 4
    for (int i = tid; i < DD * DD / 4; i += 256)
        ((float4*)ws)[i] = ((const float4*)W)[i];

    float acc[8][4];
    #pragma unroll
    for (int r = 0; r < 8; r++)
        #pragma unroll
        for (int c = 0; c < 4; c++) acc[r][c] = 0.0f;

    const int lr  = tid >> 2;        // 0..63 : row to load
    const int lk4 = (tid & 3) * 4;   // 0,4,8,12 : k offset within chunk

    for (int k0 = 0; k0 < DD; k0 += 16) {
        __syncthreads();   // protect xs from previous iter (and W load on iter 0)
        int gr = row0 + lr;
        float4 v = make_float4(0.f, 0.f, 0.f, 0.f);
        if (gr < n) v = *(const float4*)&A[gr * DD + k0 + lk4];
        xs[(lk4 + 0) * XS_PITCH + lr] = v.x;
        xs[(lk4 + 1) * XS_PITCH + lr] = v.y;
        xs[(lk4 + 2) * XS_PITCH + lr] = v.z;
        xs[(lk4 + 3) * XS_PITCH + lr] = v.w;
        __syncthreads();

        #pragma unroll
        for (int kk = 0; kk < 16; kk++) {
            float4 wv = *(float4*)&ws[(k0 + kk) * DD + tx * 4];
            float4 xa = *(float4*)&xs[kk * XS_PITCH + ty * 8];
            float4 xb = *(float4*)&xs[kk * XS_PITCH + ty * 8 + 4];
            float xr[8] = {xa.x, xa.y, xa.z, xa.w, xb.x, xb.y, xb.z, xb.w};
            #pragma unroll
            for (int r = 0; r < 8; r++) {
                acc[r][0] += xr[r] * wv.x;
                acc[r][1] += xr[r] * wv.y;
                acc[r][2] += xr[r] * wv.z;
                acc[r][3] += xr[r] * wv.w;
            }
        }
    }

    #pragma unroll
    for (int r = 0; r < 8; r++) {
        int gr = row0 + ty * 8 + r;
        if (gr < n) {
            float iv = inv[gr];
            float c = iv * iv;       // 1/deg
            float4 o = make_float4(acc[r][0], acc[r][1], acc[r][2], acc[r][3]);
            *(float4*)&H[gr * DD + tx * 4] = o;
            float4 a = make_float4(o.x * c, o.y * c, o.z * c, o.w * c);
            *(float4*)&AGG[gr * DD + tx * 4] = a;
        }
    }
}

// ---------------- edge scatter: agg[dst] += h[src] * inv[src]*inv[dst] ----------------
__global__ void k_edge(const int* __restrict__ src, const int* __restrict__ dst,
                       const float* __restrict__ h, const float* __restrict__ inv,
                       float* __restrict__ agg) {
    int gtid = blockIdx.x * blockDim.x + threadIdx.x;
    int e = gtid >> 5;
    if (e >= NE) return;
    int lane = gtid & 31;
    int s = src[e], d = dst[e];
    float coef = inv[s] * inv[d];
    float4 v = *(const float4*)&h[s * DD + lane * 4];
    v.x *= coef; v.y *= coef; v.z *= coef; v.w *= coef;
    float* p = &agg[d * DD + lane * 4];
    asm volatile("red.global.add.v4.f32 [%0], {%1, %2, %3, %4};"
                 :: "l"(p), "f"(v.x), "f"(v.y), "f"(v.z), "f"(v.w)
                 : "memory");
}

// ---------------- bias + relu (in place on agg) ----------------
__global__ void k_biasrelu(float* __restrict__ agg, const float* __restrict__ b) {
    int i = blockIdx.x * blockDim.x + threadIdx.x;   // float4 index
    if (i >= NN * (DD / 4)) return;
    int cg = i & 31;                                 // column group
    float4 bb = ((const float4*)b)[cg];
    float4 v = ((float4*)agg)[i];
    v.x = fmaxf(v.x + bb.x, 0.f);
    v.y = fmaxf(v.y + bb.y, 0.f);
    v.z = fmaxf(v.z + bb.z, 0.f);
    v.w = fmaxf(v.w + bb.w, 0.f);
    ((float4*)agg)[i] = v;
}

// ---------------- fused bias + relu + column-sum pool (layer 2 epilogue) ----------------
#define POOL_ROWS 256
__global__ void k_relu_pool(const float* __restrict__ agg, const float* __restrict__ b,
                            float* __restrict__ pool) {
    int c = threadIdx.x;             // 0..127
    int r0 = blockIdx.x * POOL_ROWS;
    int r1 = min(r0 + POOL_ROWS, NN);
    float bb = b[c];
    float s = 0.f;
    for (int r = r0; r < r1; r++)
        s += fmaxf(agg[r * DD + c] + bb, 0.f);
    atomicAdd(&pool[c], s);
}

// ---------------- finalize: g = pool/N ; logits = g@Wc + bc ; log_softmax ----------------
__global__ void k_finalize(const float* __restrict__ pool, const float* __restrict__ Wc,
                           const float* __restrict__ bc, float* __restrict__ out) {
    int t = threadIdx.x;             // 0..31
    float l0 = 0.f, l1 = 0.f;
    const float invn = 1.0f / (float)NN;
    #pragma unroll
    for (int j = 0; j < 4; j++) {
        int c = t * 4 + j;
        float g = pool[c] * invn;
        l0 += g * Wc[c * NC + 0];
        l1 += g * Wc[c * NC + 1];
    }
    #pragma unroll
    for (int o = 16; o > 0; o >>= 1) {
        l0 += __shfl_down_sync(0xFFFFFFFFu, l0, o);
        l1 += __shfl_down_sync(0xFFFFFFFFu, l1, o);
    }
    if (t == 0) {
        l0 += bc[0];
        l1 += bc[1];
        float m = fmaxf(l0, l1);
        float lse = m + logf(expf(l0 - m) + expf(l1 - m));
        out[0] = l0 - lse;
        out[1] = l1 - lse;
    }
}

// ---------------- launch ----------------
extern "C" void kernel_launch(void* const* d_in, const int* in_sizes, int n_in,
                              void* d_out, int out_size) {
    const float* x  = (const float*)d_in[0];
    const int*   ei = (const int*)d_in[1];
    const float* W1 = (const float*)d_in[2];
    const float* b1 = (const float*)d_in[3];
    const float* W2 = (const float*)d_in[4];
    const float* b2 = (const float*)d_in[5];
    const float* Wc = (const float*)d_in[6];
    const float* bc = (const float*)d_in[7];
    float* out = (float*)d_out;

    const int* src = ei;
    const int* dst = ei + NE;

    float *deg, *inv, *h, *agg, *pool;
    cudaGetSymbolAddress((void**)&deg,  g_deg);
    cudaGetSymbolAddress((void**)&inv,  g_inv);
    cudaGetSymbolAddress((void**)&h,    g_h);
    cudaGetSymbolAddress((void**)&agg,  g_agg);
    cudaGetSymbolAddress((void**)&pool, g_pool);

    const int smem = (DD * DD + 16 * XS_PITCH) * (int)sizeof(float);
    cudaFuncSetAttribute(k_gemm, cudaFuncAttributeMaxDynamicSharedMemorySize, smem);

    const int nvec = NN * (DD / 4);                  // float4 elements per feature map

    // degrees + norm
    k_init<<<(NN + 255) / 256, 256>>>(deg, pool);
    k_count<<<(NE + 255) / 256, 256>>>(dst, deg);
    k_rsqrt<<<(NN + 255) / 256, 256>>>(deg, inv);

    // layer 1 (GEMM epilogue writes h and agg = h/deg)
    k_gemm<<<(NN + 63) / 64, 256, smem>>>(x, W1, inv, h, agg, NN);
    k_edge<<<(NE * 32 + 255) / 256, 256>>>(src, dst, h, inv, agg);
    k_biasrelu<<<(nvec + 255) / 256, 256>>>(agg, b1);

    // layer 2
    k_gemm<<<(NN + 63) / 64, 256, smem>>>(agg, W2, inv, h, agg, NN);
    k_edge<<<(NE * 32 + 255) / 256, 256>>>(src, dst, h, inv, agg);

    // pool + classifier + log_softmax
    k_relu_pool<<<(NN + POOL_ROWS - 1) / POOL_ROWS, DD>>>(agg, b2, pool);
    k_finalize<<<1, 32>>>(pool, Wc, bc, out);
}

// round 3
// speedup vs baseline: 1.0199x; 1.0199x over previous
#include <cuda_runtime.h>
#include <cuda_bf16.h>
#include <math.h>

// Problem constants
#define NN 50000
#define NE 800000
#define DD 128
#define NC 2
#define SCAN_T 1024
#define SCAN_CH 49   // ceil(NN / SCAN_T)

// ---------------- scratch (static device memory; no allocation) ----------------
__device__ int   g_cnt[NN];        // in-degree (edges only)
__device__ int   g_offs[NN + 1];   // CSR row offsets
__device__ int   g_cursor[NN];     // scatter cursors
__device__ int   g_esrc[NE];       // permuted edge sources
__device__ float g_ecoef[NE];      // per-edge coefficient inv[s]*inv[d]
__device__ float g_inv[NN];        // deg^{-1/2} (deg includes self loop)
__device__ float g_h[NN * DD];     // GEMM output (h = in @ W)
__device__ float g_agg[NN * DD];   // post-ReLU activations (layer 1 output)
__device__ float g_pool[DD];       // column sums for mean pool

// ---------------- zero: cnt = 0, pool = 0 ----------------
__global__ void k_zero(int* cnt, float* pool) {
    int i = blockIdx.x * blockDim.x + threadIdx.x;
    if (i < NN) cnt[i] = 0;
    if (i < DD) pool[i] = 0.0f;
}

// ---------------- count in-degrees over dst (int) ----------------
__global__ void k_count(const int* __restrict__ dst, int* __restrict__ cnt) {
    int e = blockIdx.x * blockDim.x + threadIdx.x;
    if (e < NE) atomicAdd(&cnt[dst[e]], 1);
}

// ---------------- single-block scan: offs, cursor, inv ----------------
__global__ void __launch_bounds__(SCAN_T)
k_scan(const int* __restrict__ cnt, int* __restrict__ offs,
       int* __restrict__ cursor, float* __restrict__ inv) {
    __shared__ int ssum[SCAN_T];
    int t = threadIdx.x;
    int c0 = t * SCAN_CH;
    int c1 = min(c0 + SCAN_CH, NN);
    int s = 0;
    for (int i = c0; i < c1; i++) s += cnt[i];
    ssum[t] = s;
    __syncthreads();
    // Hillis-Steele inclusive scan
    for (int off = 1; off < SCAN_T; off <<= 1) {
        int u = (t >= off) ? ssum[t - off] : 0;
        __syncthreads();
        ssum[t] += u;
        __syncthreads();
    }
    int run = ssum[t] - s;   // exclusive prefix for this chunk
    for (int i = c0; i < c1; i++) {
        offs[i] = run;
        cursor[i] = run;
        inv[i] = rsqrtf((float)cnt[i] + 1.0f);
        run += cnt[i];
    }
    if (t == SCAN_T - 1) offs[NN] = NE;
}

// ---------------- scatter edges into CSR bins, precompute coef ----------------
__global__ void k_scatter(const int* __restrict__ src, const int* __restrict__ dst,
                          const float* __restrict__ inv,
                          int* __restrict__ cursor,
                          int* __restrict__ esrc, float* __restrict__ ecoef) {
    int e = blockIdx.x * blockDim.x + threadIdx.x;
    if (e >= NE) return;
    int s = src[e], d = dst[e];
    int pos = atomicAdd(&cursor[d], 1);
    esrc[pos] = s;
    ecoef[pos] = inv[s] * inv[d];
}

// ---------------- GEMM: H[n,128] = A[n,128] @ W[128,128] ----------------
// Block: 64 rows x 128 cols, 256 threads. Full W in smem (64KB).
#define XS_PITCH 68
__global__ void __launch_bounds__(256, 3)
k_gemm(const float* __restrict__ A, const float* __restrict__ W,
       float* __restrict__ H, int n) {
    extern __shared__ float sm[];
    float* ws = sm;                 // 128*128
    float* xs = sm + DD * DD;       // 16 * XS_PITCH

    const int tid = threadIdx.x;
    const int tx  = tid & 31;       // col group -> cols tx*4 .. tx*4+3
    const int ty  = tid >> 5;       // row group -> rows ty*8 .. ty*8+7
    const int row0 = blockIdx.x * 64;

    #pragma unroll 4
    for (int i = tid; i < DD * DD / 4; i += 256)
        ((float4*)ws)[i] = ((const float4*)W)[i];

    float acc[8][4];
    #pragma unroll
    for (int r = 0; r < 8; r++)
        #pragma unroll
        for (int c = 0; c < 4; c++) acc[r][c] = 0.0f;

    const int lr  = tid >> 2;        // 0..63 : row to load
    const int lk4 = (tid & 3) * 4;   // 0,4,8,12 : k offset within chunk

    for (int k0 = 0; k0 < DD; k0 += 16) {
        __syncthreads();
        int gr = row0 + lr;
        float4 v = make_float4(0.f, 0.f, 0.f, 0.f);
        if (gr < n) v = *(const float4*)&A[gr * DD + k0 + lk4];
        xs[(lk4 + 0) * XS_PITCH + lr] = v.x;
        xs[(lk4 + 1) * XS_PITCH + lr] = v.y;
        xs[(lk4 + 2) * XS_PITCH + lr] = v.z;
        xs[(lk4 + 3) * XS_PITCH + lr] = v.w;
        __syncthreads();

        #pragma unroll
        for (int kk = 0; kk < 16; kk++) {
            float4 wv = *(float4*)&ws[(k0 + kk) * DD + tx * 4];
            float4 xa = *(float4*)&xs[kk * XS_PITCH + ty * 8];
            float4 xb = *(float4*)&xs[kk * XS_PITCH + ty * 8 + 4];
            float xr[8] = {xa.x, xa.y, xa.z, xa.w, xb.x, xb.y, xb.z, xb.w};
            #pragma unroll
            for (int r = 0; r < 8; r++) {
                acc[r][0] += xr[r] * wv.x;
                acc[r][1] += xr[r] * wv.y;
                acc[r][2] += xr[r] * wv.z;
                acc[r][3] += xr[r] * wv.w;
            }
        }
    }

    #pragma unroll
    for (int r = 0; r < 8; r++) {
        int gr = row0 + ty * 8 + r;
        if (gr < n) {
            float4 o = make_float4(acc[r][0], acc[r][1], acc[r][2], acc[r][3]);
            *(float4*)&H[gr * DD + tx * 4] = o;
        }
    }
}

// ---------------- CSR edge aggregation helper ----------------
// warp handles node d: acc = h[d]/deg + sum_e coef*h[src_e]; returns acc (lane cols lane*4..+3)
__device__ __forceinline__ float4 agg_node(
    int d, int lane,
    const int* __restrict__ offs, const int* __restrict__ esrc,
    const float* __restrict__ ecoef, const float* __restrict__ h,
    const float* __restrict__ inv)
{
    float invd = inv[d];
    float selfc = invd * invd;
    float4 sv = *(const float4*)&h[d * DD + lane * 4];
    float ax = sv.x * selfc, ay = sv.y * selfc, az = sv.z * selfc, aw = sv.w * selfc;
    float bx = 0.f, by = 0.f, bz = 0.f, bw = 0.f;

    int beg = offs[d], end = offs[d + 1];
    int i = beg;
    for (; i + 1 < end; i += 2) {
        int s0 = __ldg(&esrc[i]);
        int s1 = __ldg(&esrc[i + 1]);
        float c0 = __ldg(&ecoef[i]);
        float c1 = __ldg(&ecoef[i + 1]);
        float4 v0 = *(const float4*)&h[s0 * DD + lane * 4];
        float4 v1 = *(const float4*)&h[s1 * DD + lane * 4];
        ax += c0 * v0.x; ay += c0 * v0.y; az += c0 * v0.z; aw += c0 * v0.w;
        bx += c1 * v1.x; by += c1 * v1.y; bz += c1 * v1.z; bw += c1 * v1.w;
    }
    if (i < end) {
        int s0 = __ldg(&esrc[i]);
        float c0 = __ldg(&ecoef[i]);
        float4 v0 = *(const float4*)&h[s0 * DD + lane * 4];
        ax += c0 * v0.x; ay += c0 * v0.y; az += c0 * v0.z; aw += c0 * v0.w;
    }
    return make_float4(ax + bx, ay + by, az + bz, aw + bw);
}

// ---------------- layer 1: agg = relu(aggregate + b1) ----------------
__global__ void __launch_bounds__(256)
k_edge1(const int* __restrict__ offs, const int* __restrict__ esrc,
        const float* __restrict__ ecoef, const float* __restrict__ h,
        const float* __restrict__ inv, const float* __restrict__ b,
        float* __restrict__ out) {
    int warp = (blockIdx.x * blockDim.x + threadIdx.x) >> 5;
    if (warp >= NN) return;
    int lane = threadIdx.x & 31;
    float4 a = agg_node(warp, lane, offs, esrc, ecoef, h, inv);
    float4 bb = ((const float4*)b)[lane];
    a.x = fmaxf(a.x + bb.x, 0.f);
    a.y = fmaxf(a.y + bb.y, 0.f);
    a.z = fmaxf(a.z + bb.z, 0.f);
    a.w = fmaxf(a.w + bb.w, 0.f);
    *(float4*)&out[warp * DD + lane * 4] = a;
}

// ---------------- layer 2: pool += relu(aggregate + b2), block-level reduce ----------------
__global__ void __launch_bounds__(256)
k_edge2_pool(const int* __restrict__ offs, const int* __restrict__ esrc,
             const float* __restrict__ ecoef, const float* __restrict__ h,
             const float* __restrict__ inv, const float* __restrict__ b,
             float* __restrict__ pool) {
    __shared__ float ps[DD];
    int tid = threadIdx.x;
    if (tid < DD) ps[tid] = 0.0f;
    __syncthreads();

    int warp = (blockIdx.x * blockDim.x + tid) >> 5;
    int lane = tid & 31;
    if (warp < NN) {
        float4 a = agg_node(warp, lane, offs, esrc, ecoef, h, inv);
        float4 bb = ((const float4*)b)[lane];
        atomicAdd(&ps[lane * 4 + 0], fmaxf(a.x + bb.x, 0.f));
        atomicAdd(&ps[lane * 4 + 1], fmaxf(a.y + bb.y, 0.f));
        atomicAdd(&ps[lane * 4 + 2], fmaxf(a.z + bb.z, 0.f));
        atomicAdd(&ps[lane * 4 + 3], fmaxf(a.w + bb.w, 0.f));
    }
    __syncthreads();
    if (tid < DD) atomicAdd(&pool[tid], ps[tid]);
}

// ---------------- finalize: g = pool/N ; logits = g@Wc + bc ; log_softmax ----------------
__global__ void k_finalize(const float* __restrict__ pool, const float* __restrict__ Wc,
                           const float* __restrict__ bc, float* __restrict__ out) {
    int t = threadIdx.x;             // 0..31
    float l0 = 0.f, l1 = 0.f;
    const float invn = 1.0f / (float)NN;
    #pragma unroll
    for (int j = 0; j < 4; j++) {
        int c = t * 4 + j;
        float g = pool[c] * invn;
        l0 += g * Wc[c * NC + 0];
        l1 += g * Wc[c * NC + 1];
    }
    #pragma unroll
    for (int o = 16; o > 0; o >>= 1) {
        l0 += __shfl_down_sync(0xFFFFFFFFu, l0, o);
        l1 += __shfl_down_sync(0xFFFFFFFFu, l1, o);
    }
    if (t == 0) {
        l0 += bc[0];
        l1 += bc[1];
        float m = fmaxf(l0, l1);
        float lse = m + logf(expf(l0 - m) + expf(l1 - m));
        out[0] = l0 - lse;
        out[1] = l1 - lse;
    }
}

// ---------------- launch ----------------
extern "C" void kernel_launch(void* const* d_in, const int* in_sizes, int n_in,
                              void* d_out, int out_size) {
    const float* x  = (const float*)d_in[0];
    const int*   ei = (const int*)d_in[1];
    const float* W1 = (const float*)d_in[2];
    const float* b1 = (const float*)d_in[3];
    const float* W2 = (const float*)d_in[4];
    const float* b2 = (const float*)d_in[5];
    const float* Wc = (const float*)d_in[6];
    const float* bc = (const float*)d_in[7];
    float* out = (float*)d_out;

    const int* src = ei;
    const int* dst = ei + NE;

    int *cnt, *offs, *cursor, *esrc;
    float *ecoef, *inv, *h, *agg, *pool;
    cudaGetSymbolAddress((void**)&cnt,    g_cnt);
    cudaGetSymbolAddress((void**)&offs,   g_offs);
    cudaGetSymbolAddress((void**)&cursor, g_cursor);
    cudaGetSymbolAddress((void**)&esrc,   g_esrc);
    cudaGetSymbolAddress((void**)&ecoef,  g_ecoef);
    cudaGetSymbolAddress((void**)&inv,    g_inv);
    cudaGetSymbolAddress((void**)&h,      g_h);
    cudaGetSymbolAddress((void**)&agg,    g_agg);
    cudaGetSymbolAddress((void**)&pool,   g_pool);

    const int smem = (DD * DD + 16 * XS_PITCH) * (int)sizeof(float);
    cudaFuncSetAttribute(k_gemm, cudaFuncAttributeMaxDynamicSharedMemorySize, smem);

    // CSR build + normalization
    k_zero<<<(NN + 255) / 256, 256>>>(cnt, pool);
    k_count<<<(NE + 255) / 256, 256>>>(dst, cnt);
    k_scan<<<1, SCAN_T>>>(cnt, offs, cursor, inv);
    k_scatter<<<(NE + 255) / 256, 256>>>(src, dst, inv, cursor, esrc, ecoef);

    const int edge_grid = (NN * 32 + 255) / 256;

    // layer 1
    k_gemm<<<(NN + 63) / 64, 256, smem>>>(x, W1, h, NN);
    k_edge1<<<edge_grid, 256>>>(offs, esrc, ecoef, h, inv, b1, agg);

    // layer 2
    k_gemm<<<(NN + 63) / 64, 256, smem>>>(agg, W2, h, NN);
    k_edge2_pool<<<edge_grid, 256>>>(offs, esrc, ecoef, h, inv, b2, pool);

    // classifier + log_softmax
    k_finalize<<<1, 32>>>(pool, Wc, bc, out);
}

// round 4
// speedup vs baseline: 1.0947x; 1.0733x over previous
#include <cuda_runtime.h>
#include <cuda_bf16.h>
#include <math.h>

// Problem constants
#define NN 50000
#define NE 800000
#define DD 128
#define NC 2
#define SCAN_T 1024
#define SCAN_CH 49   // ceil(NN / SCAN_T)

// ---------------- scratch (static device memory; no allocation) ----------------
__device__ int   g_cnt[NN];        // in-degree (edges only)
__device__ int   g_offs[NN + 1];   // CSR row offsets
__device__ int   g_cursor[NN];     // scatter cursors
__device__ int2  g_adj[NE];        // (src, coef bits) per CSR slot
__device__ float g_inv[NN];        // deg^{-1/2} (deg includes self loop)
__device__ __align__(16) __nv_bfloat16 g_hb[NN * DD];  // GEMM output in bf16
__device__ float g_agg[NN * DD];   // post-ReLU activations (layer 1 output)
__device__ float g_pool[DD];       // column sums for mean pool

// ---------------- zero: cnt = 0, pool = 0 ----------------
__global__ void k_zero(int* cnt, float* pool) {
    int i = blockIdx.x * blockDim.x + threadIdx.x;
    if (i < NN) cnt[i] = 0;
    if (i < DD) pool[i] = 0.0f;
}

// ---------------- count in-degrees over dst (int) ----------------
__global__ void k_count(const int* __restrict__ dst, int* __restrict__ cnt) {
    int e = blockIdx.x * blockDim.x + threadIdx.x;
    if (e < NE) atomicAdd(&cnt[dst[e]], 1);
}

// ---------------- single-block scan: offs, cursor, inv ----------------
__global__ void __launch_bounds__(SCAN_T)
k_scan(const int* __restrict__ cnt, int* __restrict__ offs,
       int* __restrict__ cursor, float* __restrict__ inv) {
    __shared__ int ssum[SCAN_T];
    int t = threadIdx.x;
    int c0 = t * SCAN_CH;
    int c1 = min(c0 + SCAN_CH, NN);
    int s = 0;
    for (int i = c0; i < c1; i++) s += cnt[i];
    ssum[t] = s;
    __syncthreads();
    // Hillis-Steele inclusive scan
    for (int off = 1; off < SCAN_T; off <<= 1) {
        int u = (t >= off) ? ssum[t - off] : 0;
        __syncthreads();
        ssum[t] += u;
        __syncthreads();
    }
    int run = ssum[t] - s;   // exclusive prefix for this chunk
    for (int i = c0; i < c1; i++) {
        offs[i] = run;
        cursor[i] = run;
        inv[i] = rsqrtf((float)cnt[i] + 1.0f);
        run += cnt[i];
    }
    if (t == SCAN_T - 1) offs[NN] = NE;
}

// ---------------- scatter edges into CSR bins, precompute coef ----------------
__global__ void k_scatter(const int* __restrict__ src, const int* __restrict__ dst,
                          const float* __restrict__ inv,
                          int* __restrict__ cursor, int2* __restrict__ adj) {
    int e = blockIdx.x * blockDim.x + threadIdx.x;
    if (e >= NE) return;
    int s = src[e], d = dst[e];
    int pos = atomicAdd(&cursor[d], 1);
    adj[pos] = make_int2(s, __float_as_int(inv[s] * inv[d]));
}

// ---------------- GEMM: HB[n,128] = bf16(A[n,128] @ W[128,128]) ----------------
// Block: 64 rows x 128 cols, 256 threads. Full W in smem (64KB).
#define XS_PITCH 68
__global__ void __launch_bounds__(256, 3)
k_gemm(const float* __restrict__ A, const float* __restrict__ W,
       __nv_bfloat16* __restrict__ HB, int n) {
    extern __shared__ float sm[];
    float* ws = sm;                 // 128*128
    float* xs = sm + DD * DD;       // 16 * XS_PITCH

    const int tid = threadIdx.x;
    const int tx  = tid & 31;       // col group -> cols tx*4 .. tx*4+3
    const int ty  = tid >> 5;       // row group -> rows ty*8 .. ty*8+7
    const int row0 = blockIdx.x * 64;

    #pragma unroll 4
    for (int i = tid; i < DD * DD / 4; i += 256)
        ((float4*)ws)[i] = ((const float4*)W)[i];

    float acc[8][4];
    #pragma unroll
    for (int r = 0; r < 8; r++)
        #pragma unroll
        for (int c = 0; c < 4; c++) acc[r][c] = 0.0f;

    const int lr  = tid >> 2;        // 0..63 : row to load
    const int lk4 = (tid & 3) * 4;   // 0,4,8,12 : k offset within chunk

    for (int k0 = 0; k0 < DD; k0 += 16) {
        __syncthreads();
        int gr = row0 + lr;
        float4 v = make_float4(0.f, 0.f, 0.f, 0.f);
        if (gr < n) v = *(const float4*)&A[gr * DD + k0 + lk4];
        xs[(lk4 + 0) * XS_PITCH + lr] = v.x;
        xs[(lk4 + 1) * XS_PITCH + lr] = v.y;
        xs[(lk4 + 2) * XS_PITCH + lr] = v.z;
        xs[(lk4 + 3) * XS_PITCH + lr] = v.w;
        __syncthreads();

        #pragma unroll
        for (int kk = 0; kk < 16; kk++) {
            float4 wv = *(float4*)&ws[(k0 + kk) * DD + tx * 4];
            float4 xa = *(float4*)&xs[kk * XS_PITCH + ty * 8];
            float4 xb = *(float4*)&xs[kk * XS_PITCH + ty * 8 + 4];
            float xr[8] = {xa.x, xa.y, xa.z, xa.w, xb.x, xb.y, xb.z, xb.w};
            #pragma unroll
            for (int r = 0; r < 8; r++) {
                acc[r][0] += xr[r] * wv.x;
                acc[r][1] += xr[r] * wv.y;
                acc[r][2] += xr[r] * wv.z;
                acc[r][3] += xr[r] * wv.w;
            }
        }
    }

    #pragma unroll
    for (int r = 0; r < 8; r++) {
        int gr = row0 + ty * 8 + r;
        if (gr < n) {
            uint2 ob;
            __nv_bfloat162 p0 = __floats2bfloat162_rn(acc[r][0], acc[r][1]);
            __nv_bfloat162 p1 = __floats2bfloat162_rn(acc[r][2], acc[r][3]);
            ob.x = *reinterpret_cast<unsigned int*>(&p0);
            ob.y = *reinterpret_cast<unsigned int*>(&p1);
            *(uint2*)&HB[gr * DD + tx * 4] = ob;
        }
    }
}

// ---------------- bf16 row fragment -> float4 ----------------
__device__ __forceinline__ float4 bf2f4(uint2 u) {
    __nv_bfloat162 a = *reinterpret_cast<__nv_bfloat162*>(&u.x);
    __nv_bfloat162 b = *reinterpret_cast<__nv_bfloat162*>(&u.y);
    float2 fa = __bfloat1622float2(a);
    float2 fb = __bfloat1622float2(b);
    return make_float4(fa.x, fa.y, fb.x, fb.y);
}

// ---------------- CSR edge aggregation (bf16 gather, fp32 accumulate) ----------------
__device__ __forceinline__ float4 agg_node(
    int d, int lane,
    const int* __restrict__ offs, const int2* __restrict__ adj,
    const __nv_bfloat16* __restrict__ hb, const float* __restrict__ inv)
{
    float invd = inv[d];
    float selfc = invd * invd;
    float4 sv = bf2f4(*(const uint2*)&hb[d * DD + lane * 4]);
    float ax = sv.x * selfc, ay = sv.y * selfc, az = sv.z * selfc, aw = sv.w * selfc;
    float bx = 0.f, by = 0.f, bz = 0.f, bw = 0.f;

    int beg = offs[d], end = offs[d + 1];
    int i = beg;
    for (; i + 3 < end; i += 4) {
        int2 e0 = __ldg(&adj[i]);
        int2 e1 = __ldg(&adj[i + 1]);
        int2 e2 = __ldg(&adj[i + 2]);
        int2 e3 = __ldg(&adj[i + 3]);
        uint2 r0 = *(const uint2*)&hb[e0.x * DD + lane * 4];
        uint2 r1 = *(const uint2*)&hb[e1.x * DD + lane * 4];
        uint2 r2 = *(const uint2*)&hb[e2.x * DD + lane * 4];
        uint2 r3 = *(const uint2*)&hb[e3.x * DD + lane * 4];
        float c0 = __int_as_float(e0.y), c1 = __int_as_float(e1.y);
        float c2 = __int_as_float(e2.y), c3 = __int_as_float(e3.y);
        float4 v0 = bf2f4(r0), v1 = bf2f4(r1), v2 = bf2f4(r2), v3 = bf2f4(r3);
        ax += c0 * v0.x; ay += c0 * v0.y; az += c0 * v0.z; aw += c0 * v0.w;
        bx += c1 * v1.x; by += c1 * v1.y; bz += c1 * v1.z; bw += c1 * v1.w;
        ax += c2 * v2.x; ay += c2 * v2.y; az += c2 * v2.z; aw += c2 * v2.w;
        bx += c3 * v3.x; by += c3 * v3.y; bz += c3 * v3.z; bw += c3 * v3.w;
    }
    for (; i < end; i++) {
        int2 e0 = __ldg(&adj[i]);
        float c0 = __int_as_float(e0.y);
        float4 v0 = bf2f4(*(const uint2*)&hb[e0.x * DD + lane * 4]);
        ax += c0 * v0.x; ay += c0 * v0.y; az += c0 * v0.z; aw += c0 * v0.w;
    }
    return make_float4(ax + bx, ay + by, az + bz, aw + bw);
}

// ---------------- layer 1: agg = relu(aggregate + b1) ----------------
__global__ void __launch_bounds__(256)
k_edge1(const int* __restrict__ offs, const int2* __restrict__ adj,
        const __nv_bfloat16* __restrict__ hb,
        const float* __restrict__ inv, const float* __restrict__ b,
        float* __restrict__ out) {
    int warp = (blockIdx.x * blockDim.x + threadIdx.x) >> 5;
    if (warp >= NN) return;
    int lane = threadIdx.x & 31;
    float4 a = agg_node(warp, lane, offs, adj, hb, inv);
    float4 bb = ((const float4*)b)[lane];
    a.x = fmaxf(a.x + bb.x, 0.f);
    a.y = fmaxf(a.y + bb.y, 0.f);
    a.z = fmaxf(a.z + bb.z, 0.f);
    a.w = fmaxf(a.w + bb.w, 0.f);
    *(float4*)&out[warp * DD + lane * 4] = a;
}

// ---------------- layer 2: pool += relu(aggregate + b2), block-level reduce ----------------
__global__ void __launch_bounds__(256)
k_edge2_pool(const int* __restrict__ offs, const int2* __restrict__ adj,
             const __nv_bfloat16* __restrict__ hb,
             const float* __restrict__ inv, const float* __restrict__ b,
             float* __restrict__ pool) {
    __shared__ float ps[DD];
    int tid = threadIdx.x;
    if (tid < DD) ps[tid] = 0.0f;
    __syncthreads();

    int warp = (blockIdx.x * blockDim.x + tid) >> 5;
    int lane = tid & 31;
    if (warp < NN) {
        float4 a = agg_node(warp, lane, offs, adj, hb, inv);
        float4 bb = ((const float4*)b)[lane];
        atomicAdd(&ps[lane * 4 + 0], fmaxf(a.x + bb.x, 0.f));
        atomicAdd(&ps[lane * 4 + 1], fmaxf(a.y + bb.y, 0.f));
        atomicAdd(&ps[lane * 4 + 2], fmaxf(a.z + bb.z, 0.f));
        atomicAdd(&ps[lane * 4 + 3], fmaxf(a.w + bb.w, 0.f));
    }
    __syncthreads();
    if (tid < DD) atomicAdd(&pool[tid], ps[tid]);
}

// ---------------- finalize: g = pool/N ; logits = g@Wc + bc ; log_softmax ----------------
__global__ void k_finalize(const float* __restrict__ pool, const float* __restrict__ Wc,
                           const float* __restrict__ bc, float* __restrict__ out) {
    int t = threadIdx.x;             // 0..31
    float l0 = 0.f, l1 = 0.f;
    const float invn = 1.0f / (float)NN;
    #pragma unroll
    for (int j = 0; j < 4; j++) {
        int c = t * 4 + j;
        float g = pool[c] * invn;
        l0 += g * Wc[c * NC + 0];
        l1 += g * Wc[c * NC + 1];
    }
    #pragma unroll
    for (int o = 16; o > 0; o >>= 1) {
        l0 += __shfl_down_sync(0xFFFFFFFFu, l0, o);
        l1 += __shfl_down_sync(0xFFFFFFFFu, l1, o);
    }
    if (t == 0) {
        l0 += bc[0];
        l1 += bc[1];
        float m = fmaxf(l0, l1);
        float lse = m + logf(expf(l0 - m) + expf(l1 - m));
        out[0] = l0 - lse;
        out[1] = l1 - lse;
    }
}

// ---------------- launch ----------------
extern "C" void kernel_launch(void* const* d_in, const int* in_sizes, int n_in,
                              void* d_out, int out_size) {
    const float* x  = (const float*)d_in[0];
    const int*   ei = (const int*)d_in[1];
    const float* W1 = (const float*)d_in[2];
    const float* b1 = (const float*)d_in[3];
    const float* W2 = (const float*)d_in[4];
    const float* b2 = (const float*)d_in[5];
    const float* Wc = (const float*)d_in[6];
    const float* bc = (const float*)d_in[7];
    float* out = (float*)d_out;

    const int* src = ei;
    const int* dst = ei + NE;

    int *cnt, *offs, *cursor;
    int2* adj;
    float *inv, *agg, *pool;
    __nv_bfloat16* hb;
    cudaGetSymbolAddress((void**)&cnt,    g_cnt);
    cudaGetSymbolAddress((void**)&offs,   g_offs);
    cudaGetSymbolAddress((void**)&cursor, g_cursor);
    cudaGetSymbolAddress((void**)&adj,    g_adj);
    cudaGetSymbolAddress((void**)&inv,    g_inv);
    cudaGetSymbolAddress((void**)&hb,     g_hb);
    cudaGetSymbolAddress((void**)&agg,    g_agg);
    cudaGetSymbolAddress((void**)&pool,   g_pool);

    const int smem = (DD * DD + 16 * XS_PITCH) * (int)sizeof(float);
    cudaFuncSetAttribute(k_gemm, cudaFuncAttributeMaxDynamicSharedMemorySize, smem);

    // CSR build + normalization
    k_zero<<<(NN + 255) / 256, 256>>>(cnt, pool);
    k_count<<<(NE + 255) / 256, 256>>>(dst, cnt);
    k_scan<<<1, SCAN_T>>>(cnt, offs, cursor, inv);
    k_scatter<<<(NE + 255) / 256, 256>>>(src, dst, inv, cursor, adj);

    const int edge_grid = (NN * 32 + 255) / 256;

    // layer 1
    k_gemm<<<(NN + 63) / 64, 256, smem>>>(x, W1, hb, NN);
    k_edge1<<<edge_grid, 256>>>(offs, adj, hb, inv, b1, agg);

    // layer 2
    k_gemm<<<(NN + 63) / 64, 256, smem>>>(agg, W2, hb, NN);
    k_edge2_pool<<<edge_grid, 256>>>(offs, adj, hb, inv, b2, pool);

    // classifier + log_softmax
    k_finalize<<<1, 32>>>(pool, Wc, bc, out);
}